// round 1
// baseline (speedup 1.0000x reference)
#include <cuda_runtime.h>
#include <math.h>

// Problem constants
#define B_    2
#define T_    2048
#define D_    1024
#define H_    16
#define DH_   64
#define WIN_  256
#define E3_   3072          // 3*H*Dh
#define M_    (B_ * T_)     // 4096
#define SCALE_ 0.125f       // 64^-0.5

// Scratch (static device globals — allocation-free per harness rules)
__device__ float g_qkv[(size_t)M_ * E3_];   // [4096, 3072]
__device__ float g_att[(size_t)M_ * D_];    // [4096, 1024]

// ---------------------------------------------------------------------------
// NT GEMM: C[m,n] = sum_k A[m,k] * B[n,k]
// A: [M,K] row-major, B: [N,K] row-major. 64x64 tile, BK=16, 256 threads,
// 4x4 register micro-tile per thread.
// ---------------------------------------------------------------------------
__global__ __launch_bounds__(256) void gemm_nt(const float* __restrict__ A,
                                               const float* __restrict__ B,
                                               float* __restrict__ C,
                                               int M, int N, int K) {
    __shared__ __align__(16) float As[16][68];   // [k][m], pitch 68 (16B-aligned rows)
    __shared__ __align__(16) float Bs[16][68];   // [k][n]

    const int tid = threadIdx.x;
    const int tx = tid & 15;         // n-direction
    const int ty = tid >> 4;         // m-direction
    const int m0 = blockIdx.y << 6;
    const int n0 = blockIdx.x << 6;

    const int lr = tid >> 2;         // 0..63 (tile row)
    const int lk = (tid & 3) << 2;   // 0,4,8,12 (k sub-chunk)

    const float* Ap = A + (size_t)(m0 + lr) * K + lk;
    const float* Bp = B + (size_t)(n0 + lr) * K + lk;

    float acc[4][4];
#pragma unroll
    for (int i = 0; i < 4; i++)
#pragma unroll
        for (int j = 0; j < 4; j++) acc[i][j] = 0.f;

    for (int kt = 0; kt < K; kt += 16) {
        const float4 av = *(const float4*)(Ap + kt);
        const float4 bv = *(const float4*)(Bp + kt);
        As[lk + 0][lr] = av.x; As[lk + 1][lr] = av.y;
        As[lk + 2][lr] = av.z; As[lk + 3][lr] = av.w;
        Bs[lk + 0][lr] = bv.x; Bs[lk + 1][lr] = bv.y;
        Bs[lk + 2][lr] = bv.z; Bs[lk + 3][lr] = bv.w;
        __syncthreads();

#pragma unroll
        for (int k = 0; k < 16; k++) {
            const float4 a = *(const float4*)&As[k][ty << 2];
            const float4 b = *(const float4*)&Bs[k][tx << 2];
            acc[0][0] += a.x * b.x; acc[0][1] += a.x * b.y;
            acc[0][2] += a.x * b.z; acc[0][3] += a.x * b.w;
            acc[1][0] += a.y * b.x; acc[1][1] += a.y * b.y;
            acc[1][2] += a.y * b.z; acc[1][3] += a.y * b.w;
            acc[2][0] += a.z * b.x; acc[2][1] += a.z * b.y;
            acc[2][2] += a.z * b.z; acc[2][3] += a.z * b.w;
            acc[3][0] += a.w * b.x; acc[3][1] += a.w * b.y;
            acc[3][2] += a.w * b.z; acc[3][3] += a.w * b.w;
        }
        __syncthreads();
    }

#pragma unroll
    for (int i = 0; i < 4; i++) {
        float4 o = make_float4(acc[i][0], acc[i][1], acc[i][2], acc[i][3]);
        *(float4*)(C + (size_t)(m0 + (ty << 2) + i) * N + n0 + (tx << 2)) = o;
    }
}

// ---------------------------------------------------------------------------
// Sliding-window causal attention over g_qkv, flash-style online softmax.
// One block = (64 queries) x (head) x (batch). 256 threads, 4x4 micro-tile.
// Smem (dynamic, ~66 KB):
//   Qs [64 d][64 q]   (transposed)
//   Ks [64 d][64 k]   (transposed)
//   Vs [64 k][64 d]
//   S  [64 q][68]     (scores -> probabilities)
//   mrow/lrow/crow [64] each
// ---------------------------------------------------------------------------
__global__ __launch_bounds__(256) void attn_kernel(const float* __restrict__ qkv,
                                                   float* __restrict__ outp) {
    extern __shared__ __align__(16) float sm[];
    float* Qs   = sm;                 // 4096
    float* Ks   = sm + 4096;          // 4096
    float* Vs   = sm + 8192;          // 4096
    float* S    = sm + 12288;         // 64*68 = 4352
    float* mrow = S + 64 * 68;        // 64
    float* lrow = mrow + 64;          // 64
    float* crow = lrow + 64;          // 64

    const int tid = threadIdx.x;
    const int tx = tid & 15;          // head-dim / key direction
    const int ty = tid >> 4;          // query direction
    const int q0 = blockIdx.x << 6;
    const int h  = blockIdx.y;
    const int b  = blockIdx.z;

    // Q row t, dim d lives at base + t*E3_ + d ; K at +D_ ; V at +2*D_
    const float* base = qkv + (size_t)b * T_ * E3_ + h * DH_;

    if (tid < 64) { mrow[tid] = -1e30f; lrow[tid] = 0.f; }

    // Load Q tile transposed: Qs[d][q]
#pragma unroll
    for (int u = 0; u < 4; u++) {
        const int s  = tid + (u << 8);
        const int r  = s & 63;        // query row (consecutive across lanes -> conflict-free STS)
        const int dq = s >> 6;        // which float4 of head dim
        const float4 v = *(const float4*)(base + (size_t)(q0 + r) * E3_ + (dq << 2));
        Qs[(dq * 4 + 0) * 64 + r] = v.x;
        Qs[(dq * 4 + 1) * 64 + r] = v.y;
        Qs[(dq * 4 + 2) * 64 + r] = v.z;
        Qs[(dq * 4 + 3) * 64 + r] = v.w;
    }

    float O[4][4];
#pragma unroll
    for (int i = 0; i < 4; i++)
#pragma unroll
        for (int j = 0; j < 4; j++) O[i][j] = 0.f;

    const int c_lo = (q0 > (WIN_ - 1) ? (q0 - (WIN_ - 1)) : 0) >> 6;
    const int c_hi = q0 >> 6;

    __syncthreads();   // Q + stats visible

    for (int c = c_lo; c <= c_hi; c++) {
        const int k0 = c << 6;

        // Load K tile transposed: Ks[d][k]
#pragma unroll
        for (int u = 0; u < 4; u++) {
            const int s  = tid + (u << 8);
            const int r  = s & 63;
            const int dq = s >> 6;
            const float4 kv = *(const float4*)(base + D_ + (size_t)(k0 + r) * E3_ + (dq << 2));
            Ks[(dq * 4 + 0) * 64 + r] = kv.x;
            Ks[(dq * 4 + 1) * 64 + r] = kv.y;
            Ks[(dq * 4 + 2) * 64 + r] = kv.z;
            Ks[(dq * 4 + 3) * 64 + r] = kv.w;
        }
        // Load V tile natural: Vs[k][d] (coalesced LDG, conflict-free STS.128)
#pragma unroll
        for (int u = 0; u < 4; u++) {
            const int s  = tid + (u << 8);
            const int r  = s >> 4;
            const int dq = s & 15;
            const float4 vv = *(const float4*)(base + 2 * D_ + (size_t)(k0 + r) * E3_ + (dq << 2));
            *(float4*)&Vs[r * 64 + (dq << 2)] = vv;
        }
        __syncthreads();

        // Scores: sc[i][j] = Q[q0+ty*4+i] . K[k0+tx*4+j]
        float sc[4][4];
#pragma unroll
        for (int i = 0; i < 4; i++)
#pragma unroll
            for (int j = 0; j < 4; j++) sc[i][j] = 0.f;

#pragma unroll 16
        for (int d = 0; d < 64; d++) {
            const float4 qa = *(const float4*)&Qs[d * 64 + (ty << 2)];
            const float4 kb = *(const float4*)&Ks[d * 64 + (tx << 2)];
            sc[0][0] += qa.x * kb.x; sc[0][1] += qa.x * kb.y;
            sc[0][2] += qa.x * kb.z; sc[0][3] += qa.x * kb.w;
            sc[1][0] += qa.y * kb.x; sc[1][1] += qa.y * kb.y;
            sc[1][2] += qa.y * kb.z; sc[1][3] += qa.y * kb.w;
            sc[2][0] += qa.z * kb.x; sc[2][1] += qa.z * kb.y;
            sc[2][2] += qa.z * kb.z; sc[2][3] += qa.z * kb.w;
            sc[3][0] += qa.w * kb.x; sc[3][1] += qa.w * kb.y;
            sc[3][2] += qa.w * kb.z; sc[3][3] += qa.w * kb.w;
        }

        // Mask + stage to smem
#pragma unroll
        for (int i = 0; i < 4; i++) {
            const int qg = q0 + (ty << 2) + i;
            float4 row;
            {
                const int kg = k0 + (tx << 2);
                const int d0 = qg - kg;
                row.x = (d0 >= 0 && d0 < WIN_)         ? sc[i][0] * SCALE_ : -1e30f;
                row.y = ((d0 - 1) >= 0 && (d0 - 1) < WIN_) ? sc[i][1] * SCALE_ : -1e30f;
                row.z = ((d0 - 2) >= 0 && (d0 - 2) < WIN_) ? sc[i][2] * SCALE_ : -1e30f;
                row.w = ((d0 - 3) >= 0 && (d0 - 3) < WIN_) ? sc[i][3] * SCALE_ : -1e30f;
            }
            *(float4*)&S[((ty << 2) + i) * 68 + (tx << 2)] = row;
        }
        __syncthreads();

        // Online softmax: 4 threads per query row
        {
            const int r   = tid >> 2;
            const int seg = (tid & 3) << 4;
            float* Srow = &S[r * 68 + seg];
            float mx = -1e30f;
#pragma unroll
            for (int j = 0; j < 16; j++) mx = fmaxf(mx, Srow[j]);
            mx = fmaxf(mx, __shfl_xor_sync(0xffffffffu, mx, 1));
            mx = fmaxf(mx, __shfl_xor_sync(0xffffffffu, mx, 2));
            const float mold = mrow[r];
            const float mnew = fmaxf(mold, mx);
            float sum = 0.f;
#pragma unroll
            for (int j = 0; j < 16; j++) {
                const float p = __expf(Srow[j] - mnew);
                Srow[j] = p;
                sum += p;
            }
            sum += __shfl_xor_sync(0xffffffffu, sum, 1);
            sum += __shfl_xor_sync(0xffffffffu, sum, 2);
            if ((tid & 3) == 0) {
                const float cf = __expf(mold - mnew);   // 0 for fully-masked prior state
                crow[r] = cf;
                lrow[r] = lrow[r] * cf + sum;
                mrow[r] = mnew;
            }
        }
        __syncthreads();

        // Rescale accumulator, then O += P @ V
#pragma unroll
        for (int i = 0; i < 4; i++) {
            const float cf = crow[(ty << 2) + i];
            O[i][0] *= cf; O[i][1] *= cf; O[i][2] *= cf; O[i][3] *= cf;
        }
#pragma unroll 8
        for (int k = 0; k < 64; k++) {
            const float4 v = *(const float4*)&Vs[k * 64 + (tx << 2)];
#pragma unroll
            for (int i = 0; i < 4; i++) {
                const float p = S[((ty << 2) + i) * 68 + k];
                O[i][0] += p * v.x; O[i][1] += p * v.y;
                O[i][2] += p * v.z; O[i][3] += p * v.w;
            }
        }
        __syncthreads();   // protect Ks/Vs/S before next chunk
    }

    // Normalize and store: out[b, t, h*64 + d]
#pragma unroll
    for (int i = 0; i < 4; i++) {
        const int qg  = q0 + (ty << 2) + i;
        const float inv = 1.0f / lrow[(ty << 2) + i];
        float4 o = make_float4(O[i][0] * inv, O[i][1] * inv, O[i][2] * inv, O[i][3] * inv);
        *(float4*)(outp + (size_t)(b * T_ + qg) * D_ + h * DH_ + (tx << 2)) = o;
    }
}

// ---------------------------------------------------------------------------
// Host launcher
// ---------------------------------------------------------------------------
extern "C" void kernel_launch(void* const* d_in, const int* in_sizes, int n_in,
                              void* d_out, int out_size) {
    (void)in_sizes; (void)n_in; (void)out_size;
    const float* x     = (const float*)d_in[0];   // [B,T,D]
    const float* w_qkv = (const float*)d_in[1];   // [3072,1024]
    const float* w_out = (const float*)d_in[2];   // [1024,1024]
    float* out = (float*)d_out;                   // [B,T,D]

    float* qkvbuf = nullptr;
    float* attbuf = nullptr;
    cudaGetSymbolAddress((void**)&qkvbuf, g_qkv);
    cudaGetSymbolAddress((void**)&attbuf, g_att);

    const int attn_smem = (4096 * 3 + 64 * 68 + 3 * 64) * (int)sizeof(float);  // 67328 B
    cudaFuncSetAttribute(attn_kernel, cudaFuncAttributeMaxDynamicSharedMemorySize, attn_smem);

    // 1) QKV projection: g_qkv[m,e] = sum_d x[m,d] * w_qkv[e,d]
    gemm_nt<<<dim3(E3_ / 64, M_ / 64), 256>>>(x, w_qkv, qkvbuf, M_, E3_, D_);

    // 2) Sliding-window attention -> g_att
    attn_kernel<<<dim3(T_ / 64, H_, B_), 256, attn_smem>>>(qkvbuf, attbuf);

    // 3) Output projection: out[m,d] = sum_e g_att[m,e] * w_out[d,e]
    gemm_nt<<<dim3(D_ / 64, M_ / 64), 256>>>(attbuf, w_out, out, M_, D_, D_);
}

// round 3
// speedup vs baseline: 2.4864x; 2.4864x over previous
#include <cuda_runtime.h>
#include <cstdint>
#include <math.h>

// Problem constants
#define B_    2
#define T_    2048
#define D_    1024
#define H_    16
#define DH_   64
#define WIN_  256
#define E3_   3072          // 3*H*Dh
#define M_    (B_ * T_)     // 4096
#define SCALE_ 0.125f       // 64^-0.5

// Scratch (static device globals — allocation-free per harness rules)
__device__ float g_qkv[(size_t)M_ * E3_];   // [4096, 3072]
__device__ float g_att[(size_t)M_ * D_];    // [4096, 1024]

// ===========================================================================
// tf32 warp-MMA NT GEMM: C[m,n] = sum_k A[m,k] * B[n,k]
// A:[M,K] row-major, B:[N,K] row-major. Block tile 128x128x32, 256 threads,
// 8 warps each computing 64x32 via 4x4 grid of m16n8k8 mma.sync.
// cp.async.cg double-buffered smem pipeline.
// ===========================================================================
#define BM 128
#define BN 128
#define BK 32
#define PITCH 36            // floats per smem row (bank-conflict-free fragments)
#define TILE_FLOATS (128 * PITCH)
#define GEMM_SMEM (2 * 2 * TILE_FLOATS * 4)   // A+B, double buffer = 73728 B

__device__ __forceinline__ uint32_t smem_u32(const void* p) {
    uint32_t a;
    asm("{ .reg .u64 t; cvta.to.shared.u64 t, %1; cvt.u32.u64 %0, t; }" : "=r"(a) : "l"(p));
    return a;
}
__device__ __forceinline__ void cp_async16(uint32_t saddr, const void* gptr) {
    asm volatile("cp.async.cg.shared.global [%0], [%1], 16;" :: "r"(saddr), "l"(gptr));
}
#define CP_COMMIT() asm volatile("cp.async.commit_group;" ::: "memory")
#define CP_WAIT0()  asm volatile("cp.async.wait_group 0;" ::: "memory")

__device__ __forceinline__ uint32_t f2tf32(float f) {
    uint32_t r;
    asm("cvt.rna.tf32.f32 %0, %1;" : "=r"(r) : "f"(f));
    return r;
}
__device__ __forceinline__ void mma_tf32(float* c, const uint32_t* a, const uint32_t* b) {
    asm volatile(
        "mma.sync.aligned.m16n8k8.row.col.f32.tf32.tf32.f32 "
        "{%0,%1,%2,%3}, {%4,%5,%6,%7}, {%8,%9}, {%0,%1,%2,%3};"
        : "+f"(c[0]), "+f"(c[1]), "+f"(c[2]), "+f"(c[3])
        : "r"(a[0]), "r"(a[1]), "r"(a[2]), "r"(a[3]), "r"(b[0]), "r"(b[1]));
}

__global__ __launch_bounds__(256) void gemm_tc(const float* __restrict__ A,
                                               const float* __restrict__ B,
                                               float* __restrict__ C,
                                               int Ndim, int Kdim) {
    extern __shared__ __align__(16) float sm[];
    float* As = sm;                        // [2][128][PITCH]
    float* Bs = sm + 2 * TILE_FLOATS;      // [2][128][PITCH]
    const uint32_t As_base = smem_u32(As);
    const uint32_t Bs_base = smem_u32(Bs);

    const int tid  = threadIdx.x;
    const int wid  = tid >> 5;
    const int lane = tid & 31;
    const int g    = lane >> 2;            // group id (0..7)
    const int tg   = lane & 3;             // thread in group
    const int m0   = blockIdx.y * BM;
    const int n0   = blockIdx.x * BN;
    const int wm   = wid & 1;              // warp m-half (64 rows)
    const int wn   = wid >> 1;             // warp n-quarter (32 cols)

    const int lr = tid >> 3;               // load row 0..31 step; full 128 rows via 4 iters
    const int lf = tid & 7;                // float4 index within 32-float row

    float c[4][4][4];
#pragma unroll
    for (int mt = 0; mt < 4; mt++)
#pragma unroll
        for (int nt = 0; nt < 4; nt++)
#pragma unroll
            for (int i = 0; i < 4; i++) c[mt][nt][i] = 0.f;

    const int NK = Kdim / BK;

    // Prologue: stage tile 0 into buffer 0
    {
        const float* Ap = A + (size_t)(m0 + lr) * Kdim + lf * 4;
        const float* Bp = B + (size_t)(n0 + lr) * Kdim + lf * 4;
        const uint32_t sa = As_base + (lr * PITCH + lf * 4) * 4;
        const uint32_t sb = Bs_base + (lr * PITCH + lf * 4) * 4;
#pragma unroll
        for (int u = 0; u < 4; u++) {
            cp_async16(sa + u * 32 * PITCH * 4, Ap + (size_t)u * 32 * Kdim);
            cp_async16(sb + u * 32 * PITCH * 4, Bp + (size_t)u * 32 * Kdim);
        }
        CP_COMMIT();
    }

    for (int kt = 0; kt < NK; kt++) {
        CP_WAIT0();
        __syncthreads();

        const int cur = kt & 1;
        if (kt + 1 < NK) {   // stage next tile into other buffer
            const int nxt = cur ^ 1;
            const int kc = (kt + 1) * BK;
            const float* Ap = A + (size_t)(m0 + lr) * Kdim + kc + lf * 4;
            const float* Bp = B + (size_t)(n0 + lr) * Kdim + kc + lf * 4;
            const uint32_t sa = As_base + (nxt * TILE_FLOATS + lr * PITCH + lf * 4) * 4;
            const uint32_t sb = Bs_base + (nxt * TILE_FLOATS + lr * PITCH + lf * 4) * 4;
#pragma unroll
            for (int u = 0; u < 4; u++) {
                cp_async16(sa + u * 32 * PITCH * 4, Ap + (size_t)u * 32 * Kdim);
                cp_async16(sb + u * 32 * PITCH * 4, Bp + (size_t)u * 32 * Kdim);
            }
            CP_COMMIT();
        }

        const float* Ab = As + cur * TILE_FLOATS;
        const float* Bb = Bs + cur * TILE_FLOATS;

#pragma unroll
        for (int ks = 0; ks < 4; ks++) {
            const int kc = ks * 8;
            uint32_t af[4][4], bf[4][2];
#pragma unroll
            for (int mt = 0; mt < 4; mt++) {
                const int r = wm * 64 + mt * 16 + g;
                af[mt][0] = f2tf32(Ab[r * PITCH + kc + tg]);
                af[mt][1] = f2tf32(Ab[(r + 8) * PITCH + kc + tg]);
                af[mt][2] = f2tf32(Ab[r * PITCH + kc + tg + 4]);
                af[mt][3] = f2tf32(Ab[(r + 8) * PITCH + kc + tg + 4]);
            }
#pragma unroll
            for (int nt = 0; nt < 4; nt++) {
                const int n = wn * 32 + nt * 8 + g;
                bf[nt][0] = f2tf32(Bb[n * PITCH + kc + tg]);
                bf[nt][1] = f2tf32(Bb[n * PITCH + kc + tg + 4]);
            }
#pragma unroll
            for (int mt = 0; mt < 4; mt++)
#pragma unroll
                for (int nt = 0; nt < 4; nt++)
                    mma_tf32(c[mt][nt], af[mt], bf[nt]);
        }
        __syncthreads();
    }

    // Epilogue: write 64x32 warp tile
#pragma unroll
    for (int mt = 0; mt < 4; mt++) {
        const int row = m0 + wm * 64 + mt * 16 + g;
#pragma unroll
        for (int nt = 0; nt < 4; nt++) {
            const int col = n0 + wn * 32 + nt * 8 + 2 * tg;
            *(float2*)(C + (size_t)row * Ndim + col)       = make_float2(c[mt][nt][0], c[mt][nt][1]);
            *(float2*)(C + (size_t)(row + 8) * Ndim + col) = make_float2(c[mt][nt][2], c[mt][nt][3]);
        }
    }
}

// ===========================================================================
// Sliding-window causal attention (round-1 proven version)
// ===========================================================================
__global__ __launch_bounds__(256) void attn_kernel(const float* __restrict__ qkv,
                                                   float* __restrict__ outp) {
    extern __shared__ __align__(16) float sm[];
    float* Qs   = sm;                 // 4096
    float* Ks   = sm + 4096;          // 4096
    float* Vs   = sm + 8192;          // 4096
    float* S    = sm + 12288;         // 64*68 = 4352
    float* mrow = S + 64 * 68;        // 64
    float* lrow = mrow + 64;          // 64
    float* crow = lrow + 64;          // 64

    const int tid = threadIdx.x;
    const int tx = tid & 15;
    const int ty = tid >> 4;
    const int q0 = blockIdx.x << 6;
    const int h  = blockIdx.y;
    const int b  = blockIdx.z;

    const float* base = qkv + (size_t)b * T_ * E3_ + h * DH_;

    if (tid < 64) { mrow[tid] = -1e30f; lrow[tid] = 0.f; }

#pragma unroll
    for (int u = 0; u < 4; u++) {
        const int s  = tid + (u << 8);
        const int r  = s & 63;
        const int dq = s >> 6;
        const float4 v = *(const float4*)(base + (size_t)(q0 + r) * E3_ + (dq << 2));
        Qs[(dq * 4 + 0) * 64 + r] = v.x;
        Qs[(dq * 4 + 1) * 64 + r] = v.y;
        Qs[(dq * 4 + 2) * 64 + r] = v.z;
        Qs[(dq * 4 + 3) * 64 + r] = v.w;
    }

    float O[4][4];
#pragma unroll
    for (int i = 0; i < 4; i++)
#pragma unroll
        for (int j = 0; j < 4; j++) O[i][j] = 0.f;

    const int c_lo = (q0 > (WIN_ - 1) ? (q0 - (WIN_ - 1)) : 0) >> 6;
    const int c_hi = q0 >> 6;

    __syncthreads();

    for (int c = c_lo; c <= c_hi; c++) {
        const int k0 = c << 6;

#pragma unroll
        for (int u = 0; u < 4; u++) {
            const int s  = tid + (u << 8);
            const int r  = s & 63;
            const int dq = s >> 6;
            const float4 kv = *(const float4*)(base + D_ + (size_t)(k0 + r) * E3_ + (dq << 2));
            Ks[(dq * 4 + 0) * 64 + r] = kv.x;
            Ks[(dq * 4 + 1) * 64 + r] = kv.y;
            Ks[(dq * 4 + 2) * 64 + r] = kv.z;
            Ks[(dq * 4 + 3) * 64 + r] = kv.w;
        }
#pragma unroll
        for (int u = 0; u < 4; u++) {
            const int s  = tid + (u << 8);
            const int r  = s >> 4;
            const int dq = s & 15;
            const float4 vv = *(const float4*)(base + 2 * D_ + (size_t)(k0 + r) * E3_ + (dq << 2));
            *(float4*)&Vs[r * 64 + (dq << 2)] = vv;
        }
        __syncthreads();

        float sc[4][4];
#pragma unroll
        for (int i = 0; i < 4; i++)
#pragma unroll
            for (int j = 0; j < 4; j++) sc[i][j] = 0.f;

#pragma unroll 16
        for (int d = 0; d < 64; d++) {
            const float4 qa = *(const float4*)&Qs[d * 64 + (ty << 2)];
            const float4 kb = *(const float4*)&Ks[d * 64 + (tx << 2)];
            sc[0][0] += qa.x * kb.x; sc[0][1] += qa.x * kb.y;
            sc[0][2] += qa.x * kb.z; sc[0][3] += qa.x * kb.w;
            sc[1][0] += qa.y * kb.x; sc[1][1] += qa.y * kb.y;
            sc[1][2] += qa.y * kb.z; sc[1][3] += qa.y * kb.w;
            sc[2][0] += qa.z * kb.x; sc[2][1] += qa.z * kb.y;
            sc[2][2] += qa.z * kb.z; sc[2][3] += qa.z * kb.w;
            sc[3][0] += qa.w * kb.x; sc[3][1] += qa.w * kb.y;
            sc[3][2] += qa.w * kb.z; sc[3][3] += qa.w * kb.w;
        }

#pragma unroll
        for (int i = 0; i < 4; i++) {
            const int qg = q0 + (ty << 2) + i;
            float4 row;
            {
                const int kg = k0 + (tx << 2);
                const int d0 = qg - kg;
                row.x = (d0 >= 0 && d0 < WIN_)             ? sc[i][0] * SCALE_ : -1e30f;
                row.y = ((d0 - 1) >= 0 && (d0 - 1) < WIN_) ? sc[i][1] * SCALE_ : -1e30f;
                row.z = ((d0 - 2) >= 0 && (d0 - 2) < WIN_) ? sc[i][2] * SCALE_ : -1e30f;
                row.w = ((d0 - 3) >= 0 && (d0 - 3) < WIN_) ? sc[i][3] * SCALE_ : -1e30f;
            }
            *(float4*)&S[((ty << 2) + i) * 68 + (tx << 2)] = row;
        }
        __syncthreads();

        {
            const int r   = tid >> 2;
            const int seg = (tid & 3) << 4;
            float* Srow = &S[r * 68 + seg];
            float mx = -1e30f;
#pragma unroll
            for (int j = 0; j < 16; j++) mx = fmaxf(mx, Srow[j]);
            mx = fmaxf(mx, __shfl_xor_sync(0xffffffffu, mx, 1));
            mx = fmaxf(mx, __shfl_xor_sync(0xffffffffu, mx, 2));
            const float mold = mrow[r];
            const float mnew = fmaxf(mold, mx);
            float sum = 0.f;
#pragma unroll
            for (int j = 0; j < 16; j++) {
                const float p = __expf(Srow[j] - mnew);
                Srow[j] = p;
                sum += p;
            }
            sum += __shfl_xor_sync(0xffffffffu, sum, 1);
            sum += __shfl_xor_sync(0xffffffffu, sum, 2);
            if ((tid & 3) == 0) {
                const float cf = __expf(mold - mnew);
                crow[r] = cf;
                lrow[r] = lrow[r] * cf + sum;
                mrow[r] = mnew;
            }
        }
        __syncthreads();

#pragma unroll
        for (int i = 0; i < 4; i++) {
            const float cf = crow[(ty << 2) + i];
            O[i][0] *= cf; O[i][1] *= cf; O[i][2] *= cf; O[i][3] *= cf;
        }
#pragma unroll 8
        for (int k = 0; k < 64; k++) {
            const float4 v = *(const float4*)&Vs[k * 64 + (tx << 2)];
#pragma unroll
            for (int i = 0; i < 4; i++) {
                const float p = S[((ty << 2) + i) * 68 + k];
                O[i][0] += p * v.x; O[i][1] += p * v.y;
                O[i][2] += p * v.z; O[i][3] += p * v.w;
            }
        }
        __syncthreads();
    }

#pragma unroll
    for (int i = 0; i < 4; i++) {
        const int qg  = q0 + (ty << 2) + i;
        const float inv = 1.0f / lrow[(ty << 2) + i];
        float4 o = make_float4(O[i][0] * inv, O[i][1] * inv, O[i][2] * inv, O[i][3] * inv);
        *(float4*)(outp + (size_t)(b * T_ + qg) * D_ + h * DH_ + (tx << 2)) = o;
    }
}

// ---------------------------------------------------------------------------
// Host launcher
// ---------------------------------------------------------------------------
extern "C" void kernel_launch(void* const* d_in, const int* in_sizes, int n_in,
                              void* d_out, int out_size) {
    (void)in_sizes; (void)n_in; (void)out_size;
    const float* x     = (const float*)d_in[0];   // [B,T,D]
    const float* w_qkv = (const float*)d_in[1];   // [3072,1024]
    const float* w_out = (const float*)d_in[2];   // [1024,1024]
    float* out = (float*)d_out;                   // [B,T,D]

    float* qkvbuf = nullptr;
    float* attbuf = nullptr;
    cudaGetSymbolAddress((void**)&qkvbuf, g_qkv);
    cudaGetSymbolAddress((void**)&attbuf, g_att);

    const int attn_smem = (4096 * 3 + 64 * 68 + 3 * 64) * (int)sizeof(float);  // 67328 B
    cudaFuncSetAttribute(attn_kernel, cudaFuncAttributeMaxDynamicSharedMemorySize, attn_smem);
    cudaFuncSetAttribute(gemm_tc, cudaFuncAttributeMaxDynamicSharedMemorySize, GEMM_SMEM);

    // 1) QKV projection: g_qkv[m,e] = sum_d x[m,d] * w_qkv[e,d]
    gemm_tc<<<dim3(E3_ / BN, M_ / BM), 256, GEMM_SMEM>>>(x, w_qkv, qkvbuf, E3_, D_);

    // 2) Sliding-window attention -> g_att
    attn_kernel<<<dim3(T_ / 64, H_, B_), 256, attn_smem>>>(qkvbuf, attbuf);

    // 3) Output projection: out[m,d] = sum_e g_att[m,e] * w_out[d,e]
    gemm_tc<<<dim3(D_ / BN, M_ / BM), 256, GEMM_SMEM>>>(attbuf, w_out, out, D_, D_);
}

// round 4
// speedup vs baseline: 2.9626x; 1.1916x over previous
#include <cuda_runtime.h>
#include <cstdint>
#include <math.h>

// Problem constants
#define B_    2
#define T_    2048
#define D_    1024
#define H_    16
#define DH_   64
#define WIN_  256
#define E3_   3072          // 3*H*Dh
#define M_    (B_ * T_)     // 4096
#define SCALE_ 0.125f       // 64^-0.5

// Scratch (static device globals — allocation-free per harness rules)
__device__ float g_qkv[(size_t)M_ * E3_];     // [4096, 3072] (tf32-rounded)
__device__ float g_att[(size_t)M_ * D_];      // [4096, 1024] (tf32-rounded)
__device__ float g_xr[(size_t)M_ * D_];       // pre-rounded x
__device__ float g_wqkvr[(size_t)E3_ * D_];   // pre-rounded w_qkv
__device__ float g_woutr[(size_t)D_ * D_];    // pre-rounded w_out

// ===========================================================================
// Helpers
// ===========================================================================
__device__ __forceinline__ uint32_t smem_u32(const void* p) {
    uint32_t a;
    asm("{ .reg .u64 t; cvta.to.shared.u64 t, %1; cvt.u32.u64 %0, t; }" : "=r"(a) : "l"(p));
    return a;
}
__device__ __forceinline__ void cp_async16(uint32_t saddr, const void* gptr) {
    asm volatile("cp.async.cg.shared.global [%0], [%1], 16;" :: "r"(saddr), "l"(gptr));
}
#define CP_COMMIT() asm volatile("cp.async.commit_group;" ::: "memory")
#define CP_WAIT0()  asm volatile("cp.async.wait_group 0;" ::: "memory")

__device__ __forceinline__ float tf32r(float f) {   // round-to-nearest onto tf32 grid
    uint32_t r;
    asm("cvt.rna.tf32.f32 %0, %1;" : "=r"(r) : "f"(f));
    return __uint_as_float(r);
}
__device__ __forceinline__ void mma_tf32(float* c, const uint32_t* a, const uint32_t* b) {
    asm volatile(
        "mma.sync.aligned.m16n8k8.row.col.f32.tf32.tf32.f32 "
        "{%0,%1,%2,%3}, {%4,%5,%6,%7}, {%8,%9}, {%0,%1,%2,%3};"
        : "+f"(c[0]), "+f"(c[1]), "+f"(c[2]), "+f"(c[3])
        : "r"(a[0]), "r"(a[1]), "r"(a[2]), "r"(a[3]), "r"(b[0]), "r"(b[1]));
}

// Elementwise tf32 pre-round (float4 grid-stride)
__global__ void preround(const float* __restrict__ src, float* __restrict__ dst, int n4) {
    int i = blockIdx.x * blockDim.x + threadIdx.x;
    if (i < n4) {
        float4 v = ((const float4*)src)[i];
        v.x = tf32r(v.x); v.y = tf32r(v.y); v.z = tf32r(v.z); v.w = tf32r(v.w);
        ((float4*)dst)[i] = v;
    }
}

// ===========================================================================
// tf32 warp-MMA NT GEMM (inputs pre-rounded to tf32 grid — no in-loop cvt).
// C[m,n] = sum_k A[m,k] * B[n,k]. Block 128x128x32, 8 warps, 64x32 per warp.
// ===========================================================================
#define BM 128
#define BN 128
#define BK 32
#define PITCH 36
#define TILE_FLOATS (128 * PITCH)
#define GEMM_SMEM (2 * 2 * TILE_FLOATS * 4)

template <bool ROUND_OUT>
__global__ __launch_bounds__(256) void gemm_tc(const float* __restrict__ A,
                                               const float* __restrict__ B,
                                               float* __restrict__ C,
                                               int Ndim, int Kdim) {
    extern __shared__ __align__(16) float sm[];
    float* As = sm;
    float* Bs = sm + 2 * TILE_FLOATS;
    const uint32_t As_base = smem_u32(As);
    const uint32_t Bs_base = smem_u32(Bs);

    const int tid  = threadIdx.x;
    const int wid  = tid >> 5;
    const int lane = tid & 31;
    const int g    = lane >> 2;
    const int tg   = lane & 3;
    const int m0   = blockIdx.y * BM;
    const int n0   = blockIdx.x * BN;
    const int wm   = wid & 1;
    const int wn   = wid >> 1;

    const int lr = tid >> 3;
    const int lf = tid & 7;

    float c[4][4][4];
#pragma unroll
    for (int mt = 0; mt < 4; mt++)
#pragma unroll
        for (int nt = 0; nt < 4; nt++)
#pragma unroll
            for (int i = 0; i < 4; i++) c[mt][nt][i] = 0.f;

    const int NK = Kdim / BK;

    {
        const float* Ap = A + (size_t)(m0 + lr) * Kdim + lf * 4;
        const float* Bp = B + (size_t)(n0 + lr) * Kdim + lf * 4;
        const uint32_t sa = As_base + (lr * PITCH + lf * 4) * 4;
        const uint32_t sb = Bs_base + (lr * PITCH + lf * 4) * 4;
#pragma unroll
        for (int u = 0; u < 4; u++) {
            cp_async16(sa + u * 32 * PITCH * 4, Ap + (size_t)u * 32 * Kdim);
            cp_async16(sb + u * 32 * PITCH * 4, Bp + (size_t)u * 32 * Kdim);
        }
        CP_COMMIT();
    }

    for (int kt = 0; kt < NK; kt++) {
        CP_WAIT0();
        __syncthreads();

        const int cur = kt & 1;
        if (kt + 1 < NK) {
            const int nxt = cur ^ 1;
            const int kc = (kt + 1) * BK;
            const float* Ap = A + (size_t)(m0 + lr) * Kdim + kc + lf * 4;
            const float* Bp = B + (size_t)(n0 + lr) * Kdim + kc + lf * 4;
            const uint32_t sa = As_base + (nxt * TILE_FLOATS + lr * PITCH + lf * 4) * 4;
            const uint32_t sb = Bs_base + (nxt * TILE_FLOATS + lr * PITCH + lf * 4) * 4;
#pragma unroll
            for (int u = 0; u < 4; u++) {
                cp_async16(sa + u * 32 * PITCH * 4, Ap + (size_t)u * 32 * Kdim);
                cp_async16(sb + u * 32 * PITCH * 4, Bp + (size_t)u * 32 * Kdim);
            }
            CP_COMMIT();
        }

        const float* Ab = As + cur * TILE_FLOATS;
        const float* Bb = Bs + cur * TILE_FLOATS;

#pragma unroll
        for (int ks = 0; ks < 4; ks++) {
            const int kc = ks * 8;
            uint32_t af[4][4], bf[4][2];
#pragma unroll
            for (int mt = 0; mt < 4; mt++) {
                const int r = wm * 64 + mt * 16 + g;
                af[mt][0] = __float_as_uint(Ab[r * PITCH + kc + tg]);
                af[mt][1] = __float_as_uint(Ab[(r + 8) * PITCH + kc + tg]);
                af[mt][2] = __float_as_uint(Ab[r * PITCH + kc + tg + 4]);
                af[mt][3] = __float_as_uint(Ab[(r + 8) * PITCH + kc + tg + 4]);
            }
#pragma unroll
            for (int nt = 0; nt < 4; nt++) {
                const int n = wn * 32 + nt * 8 + g;
                bf[nt][0] = __float_as_uint(Bb[n * PITCH + kc + tg]);
                bf[nt][1] = __float_as_uint(Bb[n * PITCH + kc + tg + 4]);
            }
#pragma unroll
            for (int mt = 0; mt < 4; mt++)
#pragma unroll
                for (int nt = 0; nt < 4; nt++)
                    mma_tf32(c[mt][nt], af[mt], bf[nt]);
        }
        __syncthreads();
    }

#pragma unroll
    for (int mt = 0; mt < 4; mt++) {
        const int row = m0 + wm * 64 + mt * 16 + g;
#pragma unroll
        for (int nt = 0; nt < 4; nt++) {
            const int col = n0 + wn * 32 + nt * 8 + 2 * tg;
            float v0 = c[mt][nt][0], v1 = c[mt][nt][1];
            float v2 = c[mt][nt][2], v3 = c[mt][nt][3];
            if (ROUND_OUT) { v0 = tf32r(v0); v1 = tf32r(v1); v2 = tf32r(v2); v3 = tf32r(v3); }
            *(float2*)(C + (size_t)row * Ndim + col)       = make_float2(v0, v1);
            *(float2*)(C + (size_t)(row + 8) * Ndim + col) = make_float2(v2, v3);
        }
    }
}

// ===========================================================================
// Sliding-window attention with tf32 mma. Block = 128 queries x head x batch.
// 8 warps x 16 query rows. qkv is tf32-pre-rounded. Output tf32-rounded.
// Smem: Ks[64][68] natural, VT[64][68] transposed, Ps[128][68].
// ===========================================================================
#define AQ 128
#define APITCH 68
#define ATT_SMEM ((64 * APITCH * 2 + 128 * APITCH) * 4)   // 69632 B

__global__ __launch_bounds__(256) void attn_mma(const float* __restrict__ qkv,
                                                float* __restrict__ outp) {
    extern __shared__ __align__(16) float sm[];
    float* Ks = sm;                       // [64][68]  K natural [kseq][d]
    float* VT = sm + 64 * APITCH;         // [64][68]  V transposed [d][kseq]
    float* Ps = sm + 128 * APITCH;        // [128][68] probabilities

    const int tid  = threadIdx.x;
    const int wid  = tid >> 5;
    const int lane = tid & 31;
    const int g    = lane >> 2;
    const int tg   = lane & 3;
    const int q0   = blockIdx.x * AQ;
    const int h    = blockIdx.y;
    const int b    = blockIdx.z;
    const int qw   = q0 + wid * 16;       // warp's first query row

    const float* base = qkv + (size_t)b * T_ * E3_ + h * DH_;

    // Q fragments in registers, pre-scaled by SCALE_ (power of two: exact)
    float qa[8][4];
    {
        const float* Qr0 = base + (size_t)(qw + g) * E3_;
        const float* Qr1 = base + (size_t)(qw + 8 + g) * E3_;
#pragma unroll
        for (int ks = 0; ks < 8; ks++) {
            qa[ks][0] = Qr0[ks * 8 + tg] * SCALE_;
            qa[ks][1] = Qr1[ks * 8 + tg] * SCALE_;
            qa[ks][2] = Qr0[ks * 8 + tg + 4] * SCALE_;
            qa[ks][3] = Qr1[ks * 8 + tg + 4] * SCALE_;
        }
    }

    float O[8][4];
#pragma unroll
    for (int nt = 0; nt < 8; nt++)
#pragma unroll
        for (int i = 0; i < 4; i++) O[nt][i] = 0.f;
    float mrow[2] = {-1e30f, -1e30f};
    float lrow[2] = {0.f, 0.f};

    const int c_lo = (q0 > 255 ? q0 - 255 : 0) >> 6;
    const int c_hi = (q0 + AQ - 1) >> 6;

    for (int c = c_lo; c <= c_hi; c++) {
        const int k0 = c << 6;

        // Load K (natural) and V (transposed) chunk, 64x64 each
#pragma unroll
        for (int it = 0; it < 4; it++) {
            const int idx = tid + it * 256;      // 0..1023
            const int r = idx & 63;              // kseq row
            const int f = idx >> 6;              // float4 index 0..15
            const float4 kv = *(const float4*)(base + D_ + (size_t)(k0 + r) * E3_ + f * 4);
            *(float4*)&Ks[r * APITCH + f * 4] = kv;
            const float4 vv = *(const float4*)(base + 2 * D_ + (size_t)(k0 + r) * E3_ + f * 4);
            VT[(f * 4 + 0) * APITCH + r] = vv.x;
            VT[(f * 4 + 1) * APITCH + r] = vv.y;
            VT[(f * 4 + 2) * APITCH + r] = vv.z;
            VT[(f * 4 + 3) * APITCH + r] = vv.w;
        }
        __syncthreads();

        const bool active = !(k0 > qw + 15 || k0 < qw - 318);
        if (active) {
            // S = Q @ K^T for this warp's 16 rows x 64 keys
            float s[8][4];
#pragma unroll
            for (int nt = 0; nt < 8; nt++)
#pragma unroll
                for (int i = 0; i < 4; i++) s[nt][i] = 0.f;

#pragma unroll
            for (int ks = 0; ks < 8; ks++) {
                uint32_t a[4] = {__float_as_uint(qa[ks][0]), __float_as_uint(qa[ks][1]),
                                 __float_as_uint(qa[ks][2]), __float_as_uint(qa[ks][3])};
#pragma unroll
                for (int nt = 0; nt < 8; nt++) {
                    const float* kp = &Ks[(nt * 8 + g) * APITCH + ks * 8 + tg];
                    uint32_t bfr[2] = {__float_as_uint(kp[0]), __float_as_uint(kp[4])};
                    mma_tf32(s[nt], a, bfr);
                }
            }

            // Mask (sliding causal window)
#pragma unroll
            for (int nt = 0; nt < 8; nt++) {
#pragma unroll
                for (int p = 0; p < 2; p++) {
#pragma unroll
                    for (int j = 0; j < 2; j++) {
                        const int qr = qw + g + 8 * p;
                        const int kc = k0 + nt * 8 + 2 * tg + j;
                        const int d  = qr - kc;
                        if (!(d >= 0 && d < WIN_)) s[nt][p * 2 + j] = -1e30f;
                    }
                }
            }

            // Online softmax per row pair (rows g and g+8), quad-reduced
#pragma unroll
            for (int p = 0; p < 2; p++) {
                float mx = -1e30f;
#pragma unroll
                for (int nt = 0; nt < 8; nt++) {
                    mx = fmaxf(mx, s[nt][p * 2 + 0]);
                    mx = fmaxf(mx, s[nt][p * 2 + 1]);
                }
                mx = fmaxf(mx, __shfl_xor_sync(0xffffffffu, mx, 1));
                mx = fmaxf(mx, __shfl_xor_sync(0xffffffffu, mx, 2));
                const float mnew = fmaxf(mrow[p], mx);
                float sum = 0.f;
#pragma unroll
                for (int nt = 0; nt < 8; nt++) {
#pragma unroll
                    for (int j = 0; j < 2; j++) {
                        const float v = s[nt][p * 2 + j];
                        const float pv = (v < -5e29f) ? 0.f : __expf(v - mnew);
                        s[nt][p * 2 + j] = pv;
                        sum += pv;
                    }
                }
                sum += __shfl_xor_sync(0xffffffffu, sum, 1);
                sum += __shfl_xor_sync(0xffffffffu, sum, 2);
                const float alpha = (mrow[p] < -5e29f) ? 0.f : __expf(mrow[p] - mnew);
                lrow[p] = lrow[p] * alpha + sum;
                mrow[p] = mnew;
#pragma unroll
                for (int nt = 0; nt < 8; nt++) {
                    O[nt][p * 2 + 0] *= alpha;
                    O[nt][p * 2 + 1] *= alpha;
                }
            }

            // Write P (tf32-rounded) to smem for reuse as mma A-operand
            const int pr0 = wid * 16 + g;
            const int pr1 = pr0 + 8;
#pragma unroll
            for (int nt = 0; nt < 8; nt++) {
                *(float2*)&Ps[pr0 * APITCH + nt * 8 + 2 * tg] =
                    make_float2(tf32r(s[nt][0]), tf32r(s[nt][1]));
                *(float2*)&Ps[pr1 * APITCH + nt * 8 + 2 * tg] =
                    make_float2(tf32r(s[nt][2]), tf32r(s[nt][3]));
            }
            __syncwarp();

            // O += P @ V
#pragma unroll
            for (int ks = 0; ks < 8; ks++) {
                const float* pp0 = &Ps[pr0 * APITCH + ks * 8 + tg];
                const float* pp1 = &Ps[pr1 * APITCH + ks * 8 + tg];
                uint32_t a[4] = {__float_as_uint(pp0[0]), __float_as_uint(pp1[0]),
                                 __float_as_uint(pp0[4]), __float_as_uint(pp1[4])};
#pragma unroll
                for (int nt = 0; nt < 8; nt++) {
                    const float* vp = &VT[(nt * 8 + g) * APITCH + ks * 8 + tg];
                    uint32_t bfr[2] = {__float_as_uint(vp[0]), __float_as_uint(vp[4])};
                    mma_tf32(O[nt], a, bfr);
                }
            }
        }
        __syncthreads();
    }

    // Epilogue: normalize, round to tf32 grid (feeds out-proj), store
    const float inv0 = 1.0f / lrow[0];
    const float inv1 = 1.0f / lrow[1];
    const int row0 = b * T_ + qw + g;
    const int row1 = row0 + 8;
#pragma unroll
    for (int nt = 0; nt < 8; nt++) {
        const int col = h * DH_ + nt * 8 + 2 * tg;
        *(float2*)(outp + (size_t)row0 * D_ + col) =
            make_float2(tf32r(O[nt][0] * inv0), tf32r(O[nt][1] * inv0));
        *(float2*)(outp + (size_t)row1 * D_ + col) =
            make_float2(tf32r(O[nt][2] * inv1), tf32r(O[nt][3] * inv1));
    }
}

// ---------------------------------------------------------------------------
// Host launcher
// ---------------------------------------------------------------------------
extern "C" void kernel_launch(void* const* d_in, const int* in_sizes, int n_in,
                              void* d_out, int out_size) {
    (void)in_sizes; (void)n_in; (void)out_size;
    const float* x     = (const float*)d_in[0];   // [B,T,D]
    const float* w_qkv = (const float*)d_in[1];   // [3072,1024]
    const float* w_out = (const float*)d_in[2];   // [1024,1024]
    float* out = (float*)d_out;                   // [B,T,D]

    float *qkvbuf, *attbuf, *xr, *wqkvr, *woutr;
    cudaGetSymbolAddress((void**)&qkvbuf, g_qkv);
    cudaGetSymbolAddress((void**)&attbuf, g_att);
    cudaGetSymbolAddress((void**)&xr,     g_xr);
    cudaGetSymbolAddress((void**)&wqkvr,  g_wqkvr);
    cudaGetSymbolAddress((void**)&woutr,  g_woutr);

    cudaFuncSetAttribute(gemm_tc<true>,  cudaFuncAttributeMaxDynamicSharedMemorySize, GEMM_SMEM);
    cudaFuncSetAttribute(gemm_tc<false>, cudaFuncAttributeMaxDynamicSharedMemorySize, GEMM_SMEM);
    cudaFuncSetAttribute(attn_mma, cudaFuncAttributeMaxDynamicSharedMemorySize, ATT_SMEM);

    // 0) Pre-round inputs onto the tf32 grid (removes all in-loop cvt)
    {
        const int nx = M_ * D_ / 4, nw = E3_ * D_ / 4, no = D_ * D_ / 4;
        preround<<<(nx + 255) / 256, 256>>>(x, xr, nx);
        preround<<<(nw + 255) / 256, 256>>>(w_qkv, wqkvr, nw);
        preround<<<(no + 255) / 256, 256>>>(w_out, woutr, no);
    }

    // 1) QKV projection (output tf32-rounded for the attention mma)
    gemm_tc<true><<<dim3(E3_ / BN, M_ / BM), 256, GEMM_SMEM>>>(xr, wqkvr, qkvbuf, E3_, D_);

    // 2) Sliding-window attention (tf32 mma, output tf32-rounded)
    attn_mma<<<dim3(T_ / AQ, H_, B_), 256, ATT_SMEM>>>(qkvbuf, attbuf);

    // 3) Output projection (final fp32 output, no rounding)
    gemm_tc<false><<<dim3(D_ / BN, M_ / BM), 256, GEMM_SMEM>>>(attbuf, woutr, out, D_, D_);
}

// round 5
// speedup vs baseline: 2.9786x; 1.0054x over previous
#include <cuda_runtime.h>
#include <cstdint>
#include <math.h>

// Problem constants
#define B_    2
#define T_    2048
#define D_    1024
#define H_    16
#define DH_   64
#define WIN_  256
#define E3_   3072          // 3*H*Dh
#define M_    (B_ * T_)     // 4096
#define SCALE_ 0.125f       // 64^-0.5

// Scratch (static device globals — allocation-free per harness rules)
__device__ float g_qkv[(size_t)M_ * E3_];     // [4096, 3072] (tf32-rounded)
__device__ float g_att[(size_t)M_ * D_];      // [4096, 1024] (tf32-rounded)
__device__ float g_xr[(size_t)M_ * D_];       // pre-rounded x
__device__ float g_wqkvr[(size_t)E3_ * D_];   // pre-rounded w_qkv
__device__ float g_woutr[(size_t)D_ * D_];    // pre-rounded w_out

// ===========================================================================
// Helpers
// ===========================================================================
__device__ __forceinline__ uint32_t smem_u32(const void* p) {
    uint32_t a;
    asm("{ .reg .u64 t; cvta.to.shared.u64 t, %1; cvt.u32.u64 %0, t; }" : "=r"(a) : "l"(p));
    return a;
}
__device__ __forceinline__ void cp_async16(uint32_t saddr, const void* gptr) {
    asm volatile("cp.async.cg.shared.global [%0], [%1], 16;" :: "r"(saddr), "l"(gptr));
}
#define CP_COMMIT() asm volatile("cp.async.commit_group;" ::: "memory")
#define CP_WAIT0()  asm volatile("cp.async.wait_group 0;" ::: "memory")
#define CP_WAIT1()  asm volatile("cp.async.wait_group 1;" ::: "memory")

__device__ __forceinline__ float tf32r(float f) {   // round-to-nearest onto tf32 grid
    uint32_t r;
    asm("cvt.rna.tf32.f32 %0, %1;" : "=r"(r) : "f"(f));
    return __uint_as_float(r);
}
__device__ __forceinline__ void mma_tf32(float* c, const uint32_t* a, const uint32_t* b) {
    asm volatile(
        "mma.sync.aligned.m16n8k8.row.col.f32.tf32.tf32.f32 "
        "{%0,%1,%2,%3}, {%4,%5,%6,%7}, {%8,%9}, {%0,%1,%2,%3};"
        : "+f"(c[0]), "+f"(c[1]), "+f"(c[2]), "+f"(c[3])
        : "r"(a[0]), "r"(a[1]), "r"(a[2]), "r"(a[3]), "r"(b[0]), "r"(b[1]));
}

// Elementwise tf32 pre-round (float4 grid-stride)
__global__ void preround(const float* __restrict__ src, float* __restrict__ dst, int n4) {
    int i = blockIdx.x * blockDim.x + threadIdx.x;
    if (i < n4) {
        float4 v = ((const float4*)src)[i];
        v.x = tf32r(v.x); v.y = tf32r(v.y); v.z = tf32r(v.z); v.w = tf32r(v.w);
        ((float4*)dst)[i] = v;
    }
}

// ===========================================================================
// tf32 warp-MMA NT GEMM, 3-stage cp.async pipeline, 1 barrier/iter.
// C[m,n] = sum_k A[m,k] * B[n,k]. Block 128x128x32, 8 warps, 64x32 per warp.
// ===========================================================================
#define BM 128
#define BN 128
#define BK 32
#define PITCH 36
#define STAGE_FLOATS (2 * 128 * PITCH)            // A tile then B tile
#define NSTAGE 3
#define GEMM_SMEM (NSTAGE * STAGE_FLOATS * 4)     // 110592 B

template <bool ROUND_OUT>
__global__ __launch_bounds__(256, 2) void gemm_tc(const float* __restrict__ A,
                                                  const float* __restrict__ B,
                                                  float* __restrict__ C,
                                                  int Ndim, int Kdim) {
    extern __shared__ __align__(16) float sm[];
    const uint32_t sbase = smem_u32(sm);

    const int tid  = threadIdx.x;
    const int wid  = tid >> 5;
    const int lane = tid & 31;
    const int g    = lane >> 2;
    const int tg   = lane & 3;
    const int m0   = blockIdx.y * BM;
    const int n0   = blockIdx.x * BN;
    const int wm   = wid & 1;
    const int wn   = wid >> 1;

    const int lr = tid >> 3;     // 0..31 base row (x4 via unrolled offsets)
    const int lf = tid & 7;      // float4 slot within 32-float k-row

    // Per-thread staging addresses (stage 0); stage s adds s*STAGE_FLOATS*4
    const uint32_t sa0 = sbase + (lr * PITCH + lf * 4) * 4;
    const uint32_t sb0 = sa0 + 128 * PITCH * 4;
    const float* Ap0 = A + (size_t)(m0 + lr) * Kdim + lf * 4;
    const float* Bp0 = B + (size_t)(n0 + lr) * Kdim + lf * 4;

    float c[4][4][4];
#pragma unroll
    for (int mt = 0; mt < 4; mt++)
#pragma unroll
        for (int nt = 0; nt < 4; nt++)
#pragma unroll
            for (int i = 0; i < 4; i++) c[mt][nt][i] = 0.f;

    const int NK = Kdim / BK;

    // Prologue: stages 0 and 1 in flight
#pragma unroll
    for (int s = 0; s < 2; s++) {
        const uint32_t off = (uint32_t)s * STAGE_FLOATS * 4;
        const int kc = s * BK;
#pragma unroll
        for (int u = 0; u < 4; u++) {
            cp_async16(sa0 + off + u * 32 * PITCH * 4, Ap0 + kc + (size_t)u * 32 * Kdim);
            cp_async16(sb0 + off + u * 32 * PITCH * 4, Bp0 + kc + (size_t)u * 32 * Kdim);
        }
        CP_COMMIT();
    }

    int cs = 0;                   // compute stage
    int is = 2;                   // issue stage ((kt+2)%3)
    for (int kt = 0; kt < NK; kt++) {
        if (kt < NK - 1) CP_WAIT1(); else CP_WAIT0();   // stage kt landed
        __syncthreads();          // everyone done with buffer `is` (== kt-1 mod 3)

        if (kt + 2 < NK) {
            const uint32_t off = (uint32_t)is * STAGE_FLOATS * 4;
            const int kc = (kt + 2) * BK;
#pragma unroll
            for (int u = 0; u < 4; u++) {
                cp_async16(sa0 + off + u * 32 * PITCH * 4, Ap0 + kc + (size_t)u * 32 * Kdim);
                cp_async16(sb0 + off + u * 32 * PITCH * 4, Bp0 + kc + (size_t)u * 32 * Kdim);
            }
            CP_COMMIT();
        }

        const float* Ab = sm + cs * STAGE_FLOATS;
        const float* Bb = Ab + 128 * PITCH;

#pragma unroll
        for (int ks = 0; ks < 4; ks++) {
            const int kc = ks * 8;
            uint32_t af[4][4], bf[4][2];
#pragma unroll
            for (int mt = 0; mt < 4; mt++) {
                const int r = wm * 64 + mt * 16 + g;
                af[mt][0] = __float_as_uint(Ab[r * PITCH + kc + tg]);
                af[mt][1] = __float_as_uint(Ab[(r + 8) * PITCH + kc + tg]);
                af[mt][2] = __float_as_uint(Ab[r * PITCH + kc + tg + 4]);
                af[mt][3] = __float_as_uint(Ab[(r + 8) * PITCH + kc + tg + 4]);
            }
#pragma unroll
            for (int nt = 0; nt < 4; nt++) {
                const int n = wn * 32 + nt * 8 + g;
                bf[nt][0] = __float_as_uint(Bb[n * PITCH + kc + tg]);
                bf[nt][1] = __float_as_uint(Bb[n * PITCH + kc + tg + 4]);
            }
#pragma unroll
            for (int mt = 0; mt < 4; mt++)
#pragma unroll
                for (int nt = 0; nt < 4; nt++)
                    mma_tf32(c[mt][nt], af[mt], bf[nt]);
        }
        // no trailing barrier: next iteration's top barrier protects reuse

        cs = (cs == 2) ? 0 : cs + 1;
        is = (is == 2) ? 0 : is + 1;
    }

#pragma unroll
    for (int mt = 0; mt < 4; mt++) {
        const int row = m0 + wm * 64 + mt * 16 + g;
#pragma unroll
        for (int nt = 0; nt < 4; nt++) {
            const int col = n0 + wn * 32 + nt * 8 + 2 * tg;
            float v0 = c[mt][nt][0], v1 = c[mt][nt][1];
            float v2 = c[mt][nt][2], v3 = c[mt][nt][3];
            if (ROUND_OUT) { v0 = tf32r(v0); v1 = tf32r(v1); v2 = tf32r(v2); v3 = tf32r(v3); }
            *(float2*)(C + (size_t)row * Ndim + col)       = make_float2(v0, v1);
            *(float2*)(C + (size_t)(row + 8) * Ndim + col) = make_float2(v2, v3);
        }
    }
}

// ===========================================================================
// Sliding-window attention with tf32 mma (round-4 proven version).
// ===========================================================================
#define AQ 128
#define APITCH 68
#define ATT_SMEM ((64 * APITCH * 2 + 128 * APITCH) * 4)   // 69632 B

__global__ __launch_bounds__(256) void attn_mma(const float* __restrict__ qkv,
                                                float* __restrict__ outp) {
    extern __shared__ __align__(16) float sm[];
    float* Ks = sm;                       // [64][68]  K natural [kseq][d]
    float* VT = sm + 64 * APITCH;         // [64][68]  V transposed [d][kseq]
    float* Ps = sm + 128 * APITCH;        // [128][68] probabilities

    const int tid  = threadIdx.x;
    const int wid  = tid >> 5;
    const int lane = tid & 31;
    const int g    = lane >> 2;
    const int tg   = lane & 3;
    const int q0   = blockIdx.x * AQ;
    const int h    = blockIdx.y;
    const int b    = blockIdx.z;
    const int qw   = q0 + wid * 16;       // warp's first query row

    const float* base = qkv + (size_t)b * T_ * E3_ + h * DH_;

    // Q fragments in registers, pre-scaled by SCALE_ (power of two: exact)
    float qa[8][4];
    {
        const float* Qr0 = base + (size_t)(qw + g) * E3_;
        const float* Qr1 = base + (size_t)(qw + 8 + g) * E3_;
#pragma unroll
        for (int ks = 0; ks < 8; ks++) {
            qa[ks][0] = Qr0[ks * 8 + tg] * SCALE_;
            qa[ks][1] = Qr1[ks * 8 + tg] * SCALE_;
            qa[ks][2] = Qr0[ks * 8 + tg + 4] * SCALE_;
            qa[ks][3] = Qr1[ks * 8 + tg + 4] * SCALE_;
        }
    }

    float O[8][4];
#pragma unroll
    for (int nt = 0; nt < 8; nt++)
#pragma unroll
        for (int i = 0; i < 4; i++) O[nt][i] = 0.f;
    float mrow[2] = {-1e30f, -1e30f};
    float lrow[2] = {0.f, 0.f};

    const int c_lo = (q0 > 255 ? q0 - 255 : 0) >> 6;
    const int c_hi = (q0 + AQ - 1) >> 6;

    for (int c = c_lo; c <= c_hi; c++) {
        const int k0 = c << 6;

#pragma unroll
        for (int it = 0; it < 4; it++) {
            const int idx = tid + it * 256;
            const int r = idx & 63;
            const int f = idx >> 6;
            const float4 kv = *(const float4*)(base + D_ + (size_t)(k0 + r) * E3_ + f * 4);
            *(float4*)&Ks[r * APITCH + f * 4] = kv;
            const float4 vv = *(const float4*)(base + 2 * D_ + (size_t)(k0 + r) * E3_ + f * 4);
            VT[(f * 4 + 0) * APITCH + r] = vv.x;
            VT[(f * 4 + 1) * APITCH + r] = vv.y;
            VT[(f * 4 + 2) * APITCH + r] = vv.z;
            VT[(f * 4 + 3) * APITCH + r] = vv.w;
        }
        __syncthreads();

        const bool active = !(k0 > qw + 15 || k0 < qw - 318);
        if (active) {
            float s[8][4];
#pragma unroll
            for (int nt = 0; nt < 8; nt++)
#pragma unroll
                for (int i = 0; i < 4; i++) s[nt][i] = 0.f;

#pragma unroll
            for (int ks = 0; ks < 8; ks++) {
                uint32_t a[4] = {__float_as_uint(qa[ks][0]), __float_as_uint(qa[ks][1]),
                                 __float_as_uint(qa[ks][2]), __float_as_uint(qa[ks][3])};
#pragma unroll
                for (int nt = 0; nt < 8; nt++) {
                    const float* kp = &Ks[(nt * 8 + g) * APITCH + ks * 8 + tg];
                    uint32_t bfr[2] = {__float_as_uint(kp[0]), __float_as_uint(kp[4])};
                    mma_tf32(s[nt], a, bfr);
                }
            }

#pragma unroll
            for (int nt = 0; nt < 8; nt++) {
#pragma unroll
                for (int p = 0; p < 2; p++) {
#pragma unroll
                    for (int j = 0; j < 2; j++) {
                        const int qr = qw + g + 8 * p;
                        const int kc = k0 + nt * 8 + 2 * tg + j;
                        const int d  = qr - kc;
                        if (!(d >= 0 && d < WIN_)) s[nt][p * 2 + j] = -1e30f;
                    }
                }
            }

#pragma unroll
            for (int p = 0; p < 2; p++) {
                float mx = -1e30f;
#pragma unroll
                for (int nt = 0; nt < 8; nt++) {
                    mx = fmaxf(mx, s[nt][p * 2 + 0]);
                    mx = fmaxf(mx, s[nt][p * 2 + 1]);
                }
                mx = fmaxf(mx, __shfl_xor_sync(0xffffffffu, mx, 1));
                mx = fmaxf(mx, __shfl_xor_sync(0xffffffffu, mx, 2));
                const float mnew = fmaxf(mrow[p], mx);
                float sum = 0.f;
#pragma unroll
                for (int nt = 0; nt < 8; nt++) {
#pragma unroll
                    for (int j = 0; j < 2; j++) {
                        const float v = s[nt][p * 2 + j];
                        const float pv = (v < -5e29f) ? 0.f : __expf(v - mnew);
                        s[nt][p * 2 + j] = pv;
                        sum += pv;
                    }
                }
                sum += __shfl_xor_sync(0xffffffffu, sum, 1);
                sum += __shfl_xor_sync(0xffffffffu, sum, 2);
                const float alpha = (mrow[p] < -5e29f) ? 0.f : __expf(mrow[p] - mnew);
                lrow[p] = lrow[p] * alpha + sum;
                mrow[p] = mnew;
#pragma unroll
                for (int nt = 0; nt < 8; nt++) {
                    O[nt][p * 2 + 0] *= alpha;
                    O[nt][p * 2 + 1] *= alpha;
                }
            }

            const int pr0 = wid * 16 + g;
            const int pr1 = pr0 + 8;
#pragma unroll
            for (int nt = 0; nt < 8; nt++) {
                *(float2*)&Ps[pr0 * APITCH + nt * 8 + 2 * tg] =
                    make_float2(tf32r(s[nt][0]), tf32r(s[nt][1]));
                *(float2*)&Ps[pr1 * APITCH + nt * 8 + 2 * tg] =
                    make_float2(tf32r(s[nt][2]), tf32r(s[nt][3]));
            }
            __syncwarp();

#pragma unroll
            for (int ks = 0; ks < 8; ks++) {
                const float* pp0 = &Ps[pr0 * APITCH + ks * 8 + tg];
                const float* pp1 = &Ps[pr1 * APITCH + ks * 8 + tg];
                uint32_t a[4] = {__float_as_uint(pp0[0]), __float_as_uint(pp1[0]),
                                 __float_as_uint(pp0[4]), __float_as_uint(pp1[4])};
#pragma unroll
                for (int nt = 0; nt < 8; nt++) {
                    const float* vp = &VT[(nt * 8 + g) * APITCH + ks * 8 + tg];
                    uint32_t bfr[2] = {__float_as_uint(vp[0]), __float_as_uint(vp[4])};
                    mma_tf32(O[nt], a, bfr);
                }
            }
        }
        __syncthreads();
    }

    const float inv0 = 1.0f / lrow[0];
    const float inv1 = 1.0f / lrow[1];
    const int row0 = b * T_ + qw + g;
    const int row1 = row0 + 8;
#pragma unroll
    for (int nt = 0; nt < 8; nt++) {
        const int col = h * DH_ + nt * 8 + 2 * tg;
        *(float2*)(outp + (size_t)row0 * D_ + col) =
            make_float2(tf32r(O[nt][0] * inv0), tf32r(O[nt][1] * inv0));
        *(float2*)(outp + (size_t)row1 * D_ + col) =
            make_float2(tf32r(O[nt][2] * inv1), tf32r(O[nt][3] * inv1));
    }
}

// ---------------------------------------------------------------------------
// Host launcher
// ---------------------------------------------------------------------------
extern "C" void kernel_launch(void* const* d_in, const int* in_sizes, int n_in,
                              void* d_out, int out_size) {
    (void)in_sizes; (void)n_in; (void)out_size;
    const float* x     = (const float*)d_in[0];   // [B,T,D]
    const float* w_qkv = (const float*)d_in[1];   // [3072,1024]
    const float* w_out = (const float*)d_in[2];   // [1024,1024]
    float* out = (float*)d_out;                   // [B,T,D]

    float *qkvbuf, *attbuf, *xr, *wqkvr, *woutr;
    cudaGetSymbolAddress((void**)&qkvbuf, g_qkv);
    cudaGetSymbolAddress((void**)&attbuf, g_att);
    cudaGetSymbolAddress((void**)&xr,     g_xr);
    cudaGetSymbolAddress((void**)&wqkvr,  g_wqkvr);
    cudaGetSymbolAddress((void**)&woutr,  g_woutr);

    cudaFuncSetAttribute(gemm_tc<true>,  cudaFuncAttributeMaxDynamicSharedMemorySize, GEMM_SMEM);
    cudaFuncSetAttribute(gemm_tc<false>, cudaFuncAttributeMaxDynamicSharedMemorySize, GEMM_SMEM);
    cudaFuncSetAttribute(attn_mma, cudaFuncAttributeMaxDynamicSharedMemorySize, ATT_SMEM);

    // 0) Pre-round inputs onto the tf32 grid
    {
        const int nx = M_ * D_ / 4, nw = E3_ * D_ / 4, no = D_ * D_ / 4;
        preround<<<(nx + 255) / 256, 256>>>(x, xr, nx);
        preround<<<(nw + 255) / 256, 256>>>(w_qkv, wqkvr, nw);
        preround<<<(no + 255) / 256, 256>>>(w_out, woutr, no);
    }

    // 1) QKV projection (output tf32-rounded for the attention mma)
    gemm_tc<true><<<dim3(E3_ / BN, M_ / BM), 256, GEMM_SMEM>>>(xr, wqkvr, qkvbuf, E3_, D_);

    // 2) Sliding-window attention (tf32 mma, output tf32-rounded)
    attn_mma<<<dim3(T_ / AQ, H_, B_), 256, ATT_SMEM>>>(qkvbuf, attbuf);

    // 3) Output projection (final fp32 output, no rounding)
    gemm_tc<false><<<dim3(D_ / BN, M_ / BM), 256, GEMM_SMEM>>>(attbuf, woutr, out, D_, D_);
}

// round 6
// speedup vs baseline: 3.5091x; 1.1781x over previous
#include <cuda_runtime.h>
#include <cstdint>
#include <math.h>

// Problem constants
#define B_    2
#define T_    2048
#define D_    1024
#define H_    16
#define DH_   64
#define WIN_  256
#define E3_   3072          // 3*H*Dh
#define M_    (B_ * T_)     // 4096
#define SCALE_ 0.125f       // 64^-0.5

// Scratch (static device globals — allocation-free per harness rules)
__device__ float g_qkv[(size_t)M_ * E3_];     // [4096, 3072] natural, tf32-rounded
__device__ float g_att[(size_t)M_ * D_];      // [4096, 1024] k-PERMUTED, tf32-rounded
__device__ float g_xr[(size_t)M_ * D_];       // pre-rounded + k-permuted x
__device__ float g_wqkvr[(size_t)E3_ * D_];   // pre-rounded + k-permuted w_qkv
__device__ float g_woutr[(size_t)D_ * D_];    // pre-rounded + k-permuted w_out

// ===========================================================================
// Helpers
// ===========================================================================
__device__ __forceinline__ uint32_t smem_u32(const void* p) {
    uint32_t a;
    asm("{ .reg .u64 t; cvta.to.shared.u64 t, %1; cvt.u32.u64 %0, t; }" : "=r"(a) : "l"(p));
    return a;
}
__device__ __forceinline__ void cp_async16(uint32_t saddr, const void* gptr) {
    asm volatile("cp.async.cg.shared.global [%0], [%1], 16;" :: "r"(saddr), "l"(gptr));
}
#define CP_COMMIT() asm volatile("cp.async.commit_group;" ::: "memory")
#define CP_WAIT0()  asm volatile("cp.async.wait_group 0;" ::: "memory")

__device__ __forceinline__ float tf32r(float f) {   // round-to-nearest onto tf32 grid
    uint32_t r;
    asm("cvt.rna.tf32.f32 %0, %1;" : "=r"(r) : "f"(f));
    return __uint_as_float(r);
}
__device__ __forceinline__ void mma_tf32(float* c, const uint32_t* a, const uint32_t* b) {
    asm volatile(
        "mma.sync.aligned.m16n8k8.row.col.f32.tf32.tf32.f32 "
        "{%0,%1,%2,%3}, {%4,%5,%6,%7}, {%8,%9}, {%0,%1,%2,%3};"
        : "+f"(c[0]), "+f"(c[1]), "+f"(c[2]), "+f"(c[3])
        : "r"(a[0]), "r"(a[1]), "r"(a[2]), "r"(a[3]), "r"(b[0]), "r"(b[1]));
}

// Pre-round to tf32 grid AND permute each 8-float k-group to
// [a0,a4,a1,a5,a2,a6,a3,a7] so fragment pairs (k, k+4) are contiguous.
__global__ void preround_perm(const float* __restrict__ src, float* __restrict__ dst, int n8) {
    int i = blockIdx.x * blockDim.x + threadIdx.x;
    if (i < n8) {
        const float4 v0 = ((const float4*)src)[2 * i];
        const float4 v1 = ((const float4*)src)[2 * i + 1];
        float4 o0 = make_float4(tf32r(v0.x), tf32r(v1.x), tf32r(v0.y), tf32r(v1.y));
        float4 o1 = make_float4(tf32r(v0.z), tf32r(v1.z), tf32r(v0.w), tf32r(v1.w));
        ((float4*)dst)[2 * i] = o0;
        ((float4*)dst)[2 * i + 1] = o1;
    }
}

// ===========================================================================
// tf32 warp-MMA NT GEMM on k-permuted inputs. LDS.64 fragment loads.
// C[m,n] = sum_k A[m,k]*B[n,k]. Block 128x128x32, 8 warps, 64x32 per warp.
// 2-stage cp.async pipeline, 1 barrier/iter (round-4 proven structure).
// ===========================================================================
#define BM 128
#define BN 128
#define BK 32
#define PITCH 40                                   // floats/row: conflict-free LDS.64
#define STAGE_FLOATS (2 * 128 * PITCH)             // A tile then B tile
#define GEMM_SMEM (2 * STAGE_FLOATS * 4)           // 81920 B

template <bool ROUND_OUT>
__global__ __launch_bounds__(256, 2) void gemm_tc(const float* __restrict__ A,
                                                  const float* __restrict__ B,
                                                  float* __restrict__ C,
                                                  int Ndim, int Kdim) {
    extern __shared__ __align__(16) float sm[];
    const uint32_t sbase = smem_u32(sm);

    const int tid  = threadIdx.x;
    const int wid  = tid >> 5;
    const int lane = tid & 31;
    const int g    = lane >> 2;
    const int tg   = lane & 3;
    const int m0   = blockIdx.y * BM;
    const int n0   = blockIdx.x * BN;
    const int wm   = wid & 1;
    const int wn   = wid >> 1;

    const int lr = tid >> 3;     // staging row 0..31 (x4 via +32 offsets)
    const int lf = tid & 7;      // float4 slot within 32-float k-row

    const uint32_t sa0 = sbase + (lr * PITCH + lf * 4) * 4;
    const uint32_t sb0 = sa0 + 128 * PITCH * 4;
    const float* Ap0 = A + (size_t)(m0 + lr) * Kdim + lf * 4;
    const float* Bp0 = B + (size_t)(n0 + lr) * Kdim + lf * 4;

    float c[4][4][4];
#pragma unroll
    for (int mt = 0; mt < 4; mt++)
#pragma unroll
        for (int nt = 0; nt < 4; nt++)
#pragma unroll
            for (int i = 0; i < 4; i++) c[mt][nt][i] = 0.f;

    const int NK = Kdim / BK;

    // Prologue: stage 0
    {
#pragma unroll
        for (int u = 0; u < 4; u++) {
            cp_async16(sa0 + u * 32 * PITCH * 4, Ap0 + (size_t)u * 32 * Kdim);
            cp_async16(sb0 + u * 32 * PITCH * 4, Bp0 + (size_t)u * 32 * Kdim);
        }
        CP_COMMIT();
    }

    for (int kt = 0; kt < NK; kt++) {
        CP_WAIT0();
        __syncthreads();          // tile kt landed; everyone past tile kt-1

        if (kt + 1 < NK) {        // overlap: stage kt+1 while computing kt
            const uint32_t off = (uint32_t)((kt + 1) & 1) * STAGE_FLOATS * 4;
            const int kc = (kt + 1) * BK;
#pragma unroll
            for (int u = 0; u < 4; u++) {
                cp_async16(sa0 + off + u * 32 * PITCH * 4, Ap0 + kc + (size_t)u * 32 * Kdim);
                cp_async16(sb0 + off + u * 32 * PITCH * 4, Bp0 + kc + (size_t)u * 32 * Kdim);
            }
            CP_COMMIT();
        }

        const float* Ab = sm + (kt & 1) * STAGE_FLOATS;
        const float* Bb = Ab + 128 * PITCH;

#pragma unroll
        for (int ks = 0; ks < 4; ks++) {
            const int ko = ks * 8 + 2 * tg;        // permuted: float2 = (k=kc+tg, k=kc+tg+4)
            uint32_t af[4][4], bf[4][2];
#pragma unroll
            for (int mt = 0; mt < 4; mt++) {
                const int r = wm * 64 + mt * 16 + g;
                const float2 p0 = *(const float2*)(Ab + r * PITCH + ko);
                const float2 p1 = *(const float2*)(Ab + (r + 8) * PITCH + ko);
                af[mt][0] = __float_as_uint(p0.x);
                af[mt][1] = __float_as_uint(p1.x);
                af[mt][2] = __float_as_uint(p0.y);
                af[mt][3] = __float_as_uint(p1.y);
            }
#pragma unroll
            for (int nt = 0; nt < 4; nt++) {
                const int n = wn * 32 + nt * 8 + g;
                const float2 q = *(const float2*)(Bb + n * PITCH + ko);
                bf[nt][0] = __float_as_uint(q.x);
                bf[nt][1] = __float_as_uint(q.y);
            }
#pragma unroll
            for (int mt = 0; mt < 4; mt++)
#pragma unroll
                for (int nt = 0; nt < 4; nt++)
                    mma_tf32(c[mt][nt], af[mt], bf[nt]);
        }
    }

    // Epilogue (natural column order)
#pragma unroll
    for (int mt = 0; mt < 4; mt++) {
        const int row = m0 + wm * 64 + mt * 16 + g;
#pragma unroll
        for (int nt = 0; nt < 4; nt++) {
            const int col = n0 + wn * 32 + nt * 8 + 2 * tg;
            float v0 = c[mt][nt][0], v1 = c[mt][nt][1];
            float v2 = c[mt][nt][2], v3 = c[mt][nt][3];
            if (ROUND_OUT) { v0 = tf32r(v0); v1 = tf32r(v1); v2 = tf32r(v2); v3 = tf32r(v3); }
            *(float2*)(C + (size_t)row * Ndim + col)       = make_float2(v0, v1);
            *(float2*)(C + (size_t)(row + 8) * Ndim + col) = make_float2(v2, v3);
        }
    }
}

// ===========================================================================
// Sliding-window attention, tf32 mma, cp.async double-buffered K/V chunks,
// V kept natural (pitch 72 -> conflict-free B-fragment LDS). 1 barrier/chunk.
// Epilogue stores g_att k-PERMUTED (feeds gemm2) and tf32-rounded.
// ===========================================================================
#define AQ 128
#define KP 68                       // K pitch (floats)
#define VP 72                       // V pitch (floats)
#define KCH (64 * KP)               // 4352
#define VCH (64 * VP)               // 4608
#define PSOFF (2 * KCH + 2 * VCH)   // 17920
#define ATT_SMEM ((PSOFF + 128 * 68) * 4)   // 106496 B

__global__ __launch_bounds__(256) void attn_mma(const float* __restrict__ qkv,
                                                float* __restrict__ outp) {
    extern __shared__ __align__(16) float sm[];
    const uint32_t sbase = smem_u32(sm);
    float* Ps = sm + PSOFF;

    const int tid  = threadIdx.x;
    const int wid  = tid >> 5;
    const int lane = tid & 31;
    const int g    = lane >> 2;
    const int tg   = lane & 3;
    const int q0   = blockIdx.x * AQ;
    const int h    = blockIdx.y;
    const int b    = blockIdx.z;
    const int qw   = q0 + wid * 16;

    const float* base  = qkv + (size_t)b * T_ * E3_ + h * DH_;
    const float* baseK = base + D_;
    const float* baseV = base + 2 * D_;

    // Q fragments in registers, pre-scaled by SCALE_ (power of two: exact)
    float qa[8][4];
    {
        const float* Qr0 = base + (size_t)(qw + g) * E3_;
        const float* Qr1 = base + (size_t)(qw + 8 + g) * E3_;
#pragma unroll
        for (int ks = 0; ks < 8; ks++) {
            qa[ks][0] = Qr0[ks * 8 + tg] * SCALE_;
            qa[ks][1] = Qr1[ks * 8 + tg] * SCALE_;
            qa[ks][2] = Qr0[ks * 8 + tg + 4] * SCALE_;
            qa[ks][3] = Qr1[ks * 8 + tg + 4] * SCALE_;
        }
    }

    float O[8][4];
#pragma unroll
    for (int nt = 0; nt < 8; nt++)
#pragma unroll
        for (int i = 0; i < 4; i++) O[nt][i] = 0.f;
    float mrow[2] = {-1e30f, -1e30f};
    float lrow[2] = {0.f, 0.f};

    const int c_lo = (q0 > 255 ? q0 - 255 : 0) >> 6;
    const int c_hi = (q0 + AQ - 1) >> 6;

    const int ldr = tid >> 4;      // staging row 0..15 (x4 via +16)
    const int ldf = tid & 15;      // float4 slot 0..15

    // Issue chunk c into stage s
    auto issue = [&](int c, int s) {
        const int k0 = c << 6;
        const uint32_t kb = sbase + (uint32_t)s * KCH * 4;
        const uint32_t vb = sbase + (2 * KCH + (uint32_t)s * VCH) * 4;
#pragma unroll
        for (int u = 0; u < 4; u++) {
            const int r = ldr + u * 16;
            cp_async16(kb + (r * KP + ldf * 4) * 4, baseK + (size_t)(k0 + r) * E3_ + ldf * 4);
            cp_async16(vb + (r * VP + ldf * 4) * 4, baseV + (size_t)(k0 + r) * E3_ + ldf * 4);
        }
        CP_COMMIT();
    };

    issue(c_lo, 0);

    for (int c = c_lo; c <= c_hi; c++) {
        const int k0 = c << 6;
        const int st = (c - c_lo) & 1;
        CP_WAIT0();
        __syncthreads();                       // chunk c landed; all past chunk c-1
        if (c < c_hi) issue(c + 1, st ^ 1);

        const float* Kb = sm + st * KCH;
        const float* Vb = sm + 2 * KCH + st * VCH;

        const bool active = !(k0 > qw + 15 || k0 < qw - 318);
        if (active) {
            // S = Q @ K^T
            float s[8][4];
#pragma unroll
            for (int nt = 0; nt < 8; nt++)
#pragma unroll
                for (int i = 0; i < 4; i++) s[nt][i] = 0.f;

#pragma unroll
            for (int ks = 0; ks < 8; ks++) {
                uint32_t a[4] = {__float_as_uint(qa[ks][0]), __float_as_uint(qa[ks][1]),
                                 __float_as_uint(qa[ks][2]), __float_as_uint(qa[ks][3])};
#pragma unroll
                for (int nt = 0; nt < 8; nt++) {
                    const float* kp = &Kb[(nt * 8 + g) * KP + ks * 8 + tg];
                    uint32_t bfr[2] = {__float_as_uint(kp[0]), __float_as_uint(kp[4])};
                    mma_tf32(s[nt], a, bfr);
                }
            }

            // Sliding causal window mask
#pragma unroll
            for (int nt = 0; nt < 8; nt++) {
#pragma unroll
                for (int p = 0; p < 2; p++) {
#pragma unroll
                    for (int j = 0; j < 2; j++) {
                        const int qr = qw + g + 8 * p;
                        const int kc = k0 + nt * 8 + 2 * tg + j;
                        const int d  = qr - kc;
                        if (!(d >= 0 && d < WIN_)) s[nt][p * 2 + j] = -1e30f;
                    }
                }
            }

            // Online softmax per row (quad-reduced)
#pragma unroll
            for (int p = 0; p < 2; p++) {
                float mx = -1e30f;
#pragma unroll
                for (int nt = 0; nt < 8; nt++) {
                    mx = fmaxf(mx, s[nt][p * 2 + 0]);
                    mx = fmaxf(mx, s[nt][p * 2 + 1]);
                }
                mx = fmaxf(mx, __shfl_xor_sync(0xffffffffu, mx, 1));
                mx = fmaxf(mx, __shfl_xor_sync(0xffffffffu, mx, 2));
                const float mnew = fmaxf(mrow[p], mx);
                float sum = 0.f;
#pragma unroll
                for (int nt = 0; nt < 8; nt++) {
#pragma unroll
                    for (int j = 0; j < 2; j++) {
                        const float v = s[nt][p * 2 + j];
                        const float pv = (v < -5e29f) ? 0.f : __expf(v - mnew);
                        s[nt][p * 2 + j] = pv;
                        sum += pv;
                    }
                }
                sum += __shfl_xor_sync(0xffffffffu, sum, 1);
                sum += __shfl_xor_sync(0xffffffffu, sum, 2);
                const float alpha = (mrow[p] < -5e29f) ? 0.f : __expf(mrow[p] - mnew);
                lrow[p] = lrow[p] * alpha + sum;
                mrow[p] = mnew;
#pragma unroll
                for (int nt = 0; nt < 8; nt++) {
                    O[nt][p * 2 + 0] *= alpha;
                    O[nt][p * 2 + 1] *= alpha;
                }
            }

            // Stage P (tf32-rounded) for reuse as mma A-operand
            const int pr0 = wid * 16 + g;
            const int pr1 = pr0 + 8;
#pragma unroll
            for (int nt = 0; nt < 8; nt++) {
                *(float2*)&Ps[pr0 * 68 + nt * 8 + 2 * tg] =
                    make_float2(tf32r(s[nt][0]), tf32r(s[nt][1]));
                *(float2*)&Ps[pr1 * 68 + nt * 8 + 2 * tg] =
                    make_float2(tf32r(s[nt][2]), tf32r(s[nt][3]));
            }
            __syncwarp();

            // O += P @ V  (V natural: b-frag = V[kc+tg][n], V[kc+tg+4][n])
#pragma unroll
            for (int ks = 0; ks < 8; ks++) {
                const float* pp0 = &Ps[pr0 * 68 + ks * 8 + tg];
                const float* pp1 = &Ps[pr1 * 68 + ks * 8 + tg];
                uint32_t a[4] = {__float_as_uint(pp0[0]), __float_as_uint(pp1[0]),
                                 __float_as_uint(pp0[4]), __float_as_uint(pp1[4])};
#pragma unroll
                for (int nt = 0; nt < 8; nt++) {
                    const float* vp = &Vb[(ks * 8 + tg) * VP + nt * 8 + g];
                    uint32_t bfr[2] = {__float_as_uint(vp[0]), __float_as_uint(vp[4 * VP])};
                    mma_tf32(O[nt], a, bfr);
                }
            }
        }
        __syncthreads();   // all warps done with stage st before it is refilled
    }

    // Epilogue: normalize, tf32-round, store k-PERMUTED (slot j<4 -> 2j, else 2j-7)
    const float inv0 = 1.0f / lrow[0];
    const float inv1 = 1.0f / lrow[1];
    const int row0 = b * T_ + qw + g;
    const int row1 = row0 + 8;
    const int j0 = 2 * tg, j1 = 2 * tg + 1;
    const int s0 = (j0 < 4) ? 2 * j0 : 2 * j0 - 7;
    const int s1 = (j1 < 4) ? 2 * j1 : 2 * j1 - 7;
#pragma unroll
    for (int nt = 0; nt < 8; nt++) {
        const int colb = h * DH_ + nt * 8;
        outp[(size_t)row0 * D_ + colb + s0] = tf32r(O[nt][0] * inv0);
        outp[(size_t)row0 * D_ + colb + s1] = tf32r(O[nt][1] * inv0);
        outp[(size_t)row1 * D_ + colb + s0] = tf32r(O[nt][2] * inv1);
        outp[(size_t)row1 * D_ + colb + s1] = tf32r(O[nt][3] * inv1);
    }
}

// ---------------------------------------------------------------------------
// Host launcher
// ---------------------------------------------------------------------------
extern "C" void kernel_launch(void* const* d_in, const int* in_sizes, int n_in,
                              void* d_out, int out_size) {
    (void)in_sizes; (void)n_in; (void)out_size;
    const float* x     = (const float*)d_in[0];   // [B,T,D]
    const float* w_qkv = (const float*)d_in[1];   // [3072,1024]
    const float* w_out = (const float*)d_in[2];   // [1024,1024]
    float* out = (float*)d_out;                   // [B,T,D]

    float *qkvbuf, *attbuf, *xr, *wqkvr, *woutr;
    cudaGetSymbolAddress((void**)&qkvbuf, g_qkv);
    cudaGetSymbolAddress((void**)&attbuf, g_att);
    cudaGetSymbolAddress((void**)&xr,     g_xr);
    cudaGetSymbolAddress((void**)&wqkvr,  g_wqkvr);
    cudaGetSymbolAddress((void**)&woutr,  g_woutr);

    cudaFuncSetAttribute(gemm_tc<true>,  cudaFuncAttributeMaxDynamicSharedMemorySize, GEMM_SMEM);
    cudaFuncSetAttribute(gemm_tc<false>, cudaFuncAttributeMaxDynamicSharedMemorySize, GEMM_SMEM);
    cudaFuncSetAttribute(attn_mma, cudaFuncAttributeMaxDynamicSharedMemorySize, ATT_SMEM);

    // 0) Pre-round + k-permute GEMM inputs
    {
        const int nx = M_ * D_ / 8, nw = E3_ * D_ / 8, no = D_ * D_ / 8;
        preround_perm<<<(nx + 255) / 256, 256>>>(x, xr, nx);
        preround_perm<<<(nw + 255) / 256, 256>>>(w_qkv, wqkvr, nw);
        preround_perm<<<(no + 255) / 256, 256>>>(w_out, woutr, no);
    }

    // 1) QKV projection (natural-layout tf32-rounded output for attention)
    gemm_tc<true><<<dim3(E3_ / BN, M_ / BM), 256, GEMM_SMEM>>>(xr, wqkvr, qkvbuf, E3_, D_);

    // 2) Sliding-window attention (writes k-permuted g_att)
    attn_mma<<<dim3(T_ / AQ, H_, B_), 256, ATT_SMEM>>>(qkvbuf, attbuf);

    // 3) Output projection (final fp32 output)
    gemm_tc<false><<<dim3(D_ / BN, M_ / BM), 256, GEMM_SMEM>>>(attbuf, woutr, out, D_, D_);
}